// round 2
// baseline (speedup 1.0000x reference)
#include <cuda_runtime.h>
#include <math_constants.h>

// Problem constants (fixed shapes)
#define BATCH 8
#define LSEQ 4096
#define DDIM 1024
#define SMEM_ROWS 256      // S
#define NG 3               // ngram order
#define M_TOTAL (BATCH*LSEQ)   // 32768

// GEMM tiling
#define BM 128
#define BN 64
#define KT 16
#define NTHREADS 256

// Scratch (no cudaMalloc allowed)
__device__ int g_best[M_TOTAL * NG];   // argmax s per (row, n)
__device__ int g_pad_best[NG];         // argmax_s pos_bias[s,n] for zero-padded rows

// ---------------------------------------------------------------------------
// Kernel C: argmax of pos_bias per n (for t < 0 rows, where the ngram is zero)
// ---------------------------------------------------------------------------
__global__ void pad_best_kernel(const float* __restrict__ pb) {
    int n = threadIdx.x;
    if (n < NG) {
        float bv = -CUDART_INF_F; int bi = 0;
        for (int s = 0; s < SMEM_ROWS; s++) {
            float v = pb[s * NG + n];
            if (v > bv) { bv = v; bi = s; }
        }
        g_pad_best[n] = bi;
    }
}

// ---------------------------------------------------------------------------
// Kernel A: fused scores-GEMM + per-row argmax over s, for one n per blockIdx.y
//   scores[m, s] = dot(x[m,:], memory[s, n, :]) + pos_bias[s, n]
//   g_best[m*3+n] = argmax_s scores[m, s]   (ties -> lowest s, like jnp.argmax)
// ---------------------------------------------------------------------------
__global__ __launch_bounds__(NTHREADS)
void score_argmax_kernel(const float* __restrict__ x,
                         const float* __restrict__ mem,
                         const float* __restrict__ pb)
{
    __shared__ float As[KT][BM];       // 8 KB  (transposed: [k][row])
    __shared__ float Bs[KT][BN];       // 4 KB  (transposed: [k][col])
    __shared__ float biasSm[BN];
    __shared__ float bestVal[BM];
    __shared__ int   bestIdx[BM];

    const int tid = threadIdx.x;
    const int tx = tid & 15;           // 16 col-threads
    const int ty = tid >> 4;           // 16 row-threads
    const int m0 = blockIdx.x * BM;
    const int n  = blockIdx.y;

    if (tid < BM) { bestVal[tid] = -CUDART_INF_F; bestIdx[tid] = 0; }
    __syncthreads();

    // 4 column tiles of 64 cover all S=256 memory rows for this n
    for (int ct = 0; ct < SMEM_ROWS / BN; ct++) {
        const int s_base = ct * BN;

        if (tid < BN) biasSm[tid] = pb[(s_base + tid) * NG + n];

        float acc[8][4];
        #pragma unroll
        for (int i = 0; i < 8; i++)
            #pragma unroll
            for (int j = 0; j < 4; j++)
                acc[i][j] = 0.0f;

        for (int k0 = 0; k0 < DDIM; k0 += KT) {
            // Load A tile: 128x16 floats = 512 float4, 2 per thread
            #pragma unroll
            for (int t = 0; t < 2; t++) {
                int lid = tid + t * NTHREADS;    // 0..511
                int row = lid >> 2;
                int kc  = lid & 3;
                float4 v = *reinterpret_cast<const float4*>(
                    x + (size_t)(m0 + row) * DDIM + k0 + kc * 4);
                As[kc * 4 + 0][row] = v.x;
                As[kc * 4 + 1][row] = v.y;
                As[kc * 4 + 2][row] = v.z;
                As[kc * 4 + 3][row] = v.w;
            }
            // Load B tile: 64x16 floats = 256 float4, 1 per thread
            {
                int col = tid >> 2;
                int kc  = tid & 3;
                int srow = (s_base + col) * NG + n;   // memory[s][n] row
                float4 v = *reinterpret_cast<const float4*>(
                    mem + (size_t)srow * DDIM + k0 + kc * 4);
                Bs[kc * 4 + 0][col] = v.x;
                Bs[kc * 4 + 1][col] = v.y;
                Bs[kc * 4 + 2][col] = v.z;
                Bs[kc * 4 + 3][col] = v.w;
            }
            __syncthreads();

            #pragma unroll
            for (int k = 0; k < KT; k++) {
                float4 a0 = *reinterpret_cast<float4*>(&As[k][ty * 8 + 0]);
                float4 a1 = *reinterpret_cast<float4*>(&As[k][ty * 8 + 4]);
                float4 b0 = *reinterpret_cast<float4*>(&Bs[k][tx * 4]);
                float a[8] = {a0.x, a0.y, a0.z, a0.w, a1.x, a1.y, a1.z, a1.w};
                float b[4] = {b0.x, b0.y, b0.z, b0.w};
                #pragma unroll
                for (int i = 0; i < 8; i++)
                    #pragma unroll
                    for (int j = 0; j < 4; j++)
                        acc[i][j] = fmaf(a[i], b[j], acc[i][j]);
            }
            __syncthreads();
        }

        // Per-row argmax over this 64-column tile, merged into running best.
        #pragma unroll
        for (int i = 0; i < 8; i++) {
            int row = ty * 8 + i;
            float v  = acc[i][0] + biasSm[tx * 4 + 0];
            int  idx = s_base + tx * 4 + 0;
            #pragma unroll
            for (int j = 1; j < 4; j++) {
                float v2 = acc[i][j] + biasSm[tx * 4 + j];
                int   i2 = s_base + tx * 4 + j;
                if (v2 > v) { v = v2; idx = i2; }   // strict > keeps lowest idx on tie
            }
            // Reduce across the 16 tx lanes (stays within half-warp: lane = (ty&1)*16+tx)
            #pragma unroll
            for (int off = 1; off < 16; off <<= 1) {
                float v2 = __shfl_xor_sync(0xffffffffu, v, off);
                int   i2 = __shfl_xor_sync(0xffffffffu, idx, off);
                if (v2 > v || (v2 == v && i2 < idx)) { v = v2; idx = i2; }
            }
            if (tx == 0) {
                if (v > bestVal[row] || (v == bestVal[row] && idx < bestIdx[row])) {
                    bestVal[row] = v; bestIdx[row] = idx;
                }
            }
        }
        __syncthreads();   // protect biasSm/As/Bs reuse + bestVal visibility
    }

    if (tid < BM) {
        g_best[(size_t)(m0 + tid) * NG + n] = bestIdx[tid];
    }
}

// ---------------------------------------------------------------------------
// Kernel B: gather + sum
//   out[b,l,:] = sum_n memory[best_n(b, l+n-2), n, :]   (pad best for t<0)
// ---------------------------------------------------------------------------
__global__ void gather_kernel(const float* __restrict__ mem,
                              float* __restrict__ out)
{
    int m = blockIdx.x;                // 0..32767 (= b*LSEQ + l)
    int l = m & (LSEQ - 1);
    int tid = threadIdx.x;             // 128 threads

    int i0 = (l - 2 < 0) ? g_pad_best[0] : g_best[(size_t)(m - 2) * NG + 0];
    int i1 = (l - 1 < 0) ? g_pad_best[1] : g_best[(size_t)(m - 1) * NG + 1];
    int i2 = g_best[(size_t)m * NG + 2];

    const float4* r0 = reinterpret_cast<const float4*>(mem + ((size_t)i0 * NG + 0) * DDIM);
    const float4* r1 = reinterpret_cast<const float4*>(mem + ((size_t)i1 * NG + 1) * DDIM);
    const float4* r2 = reinterpret_cast<const float4*>(mem + ((size_t)i2 * NG + 2) * DDIM);
    float4* o = reinterpret_cast<float4*>(out + (size_t)m * DDIM);

    #pragma unroll
    for (int d = tid; d < DDIM / 4; d += 128) {
        float4 a = r0[d], b = r1[d], c = r2[d];
        float4 s;
        s.x = (a.x + b.x) + c.x;   // same order as jnp sum over n
        s.y = (a.y + b.y) + c.y;
        s.z = (a.z + b.z) + c.z;
        s.w = (a.w + b.w) + c.w;
        o[d] = s;
    }
}

// ---------------------------------------------------------------------------
extern "C" void kernel_launch(void* const* d_in, const int* in_sizes, int n_in,
                              void* d_out, int out_size)
{
    const float* x   = (const float*)d_in[0];   // (8, 4096, 1024) f32
    const float* mem = (const float*)d_in[1];   // (256, 3, 1024) f32
    const float* pb  = (const float*)d_in[2];   // (256, 3) f32
    float* out = (float*)d_out;                 // (8, 4096, 1024) f32

    pad_best_kernel<<<1, 32>>>(pb);

    dim3 grid(M_TOTAL / BM, NG);
    score_argmax_kernel<<<grid, NTHREADS>>>(x, mem, pb);

    gather_kernel<<<M_TOTAL, 128>>>(mem, out);
}